// round 6
// baseline (speedup 1.0000x reference)
#include <cuda_runtime.h>
#include <cuda_bf16.h>
#include <math.h>
#include <stdint.h>

// ---------------------------------------------------------------------------
// Problem constants
// ---------------------------------------------------------------------------
#define BS 4
#define NN 256
#define DX 256
#define HH 8
#define DF 32
#define DFF 1024
#define ROWS (BS * NN)            // 1024
#define HROWS (ROWS / 2)          // 512 rows per half (2 batches)
#define EPS 1e-5f

// ---------------------------------------------------------------------------
// Device scratch (no allocations allowed)
// ---------------------------------------------------------------------------
__device__ float g_Q [ROWS * DX];
__device__ float g_K [ROWS * DX];
__device__ float g_V [ROWS * DX];
__device__ float g_T [ROWS * DX];
__device__ float g_X1[ROWS * DX];
__device__ float g_H [ROWS * DFF];
__device__ float g_P [2 * 4 * HROWS * DX];   // split-K partials, per-half regions

// ---------------------------------------------------------------------------
// Double-buffered SGEMM: BM=BN=64, BK=16, 128 threads, 8x4 micro-tile,
// ping-pong SMEM, 1 sync/iter.
// mode 0: fused-N (blockIdx.x spans matrices; bias added here)
// mode 1: split-K (blockIdx.z = K-chunk; partial to C + z*M*N; bias deferred)
// ---------------------------------------------------------------------------
struct GArgs {
    const float* A;
    const float* B[3];
    const float* bias[3];
    float* C[3];
    int M, N, lda;      // N = per-matrix width; lda = A row stride
    int kPerZ;
    int relu, mode;
};

#define BM 64
#define BN 64
#define BKK 16

__global__ __launch_bounds__(128)
void sgemm_kernel(GArgs a)
{
    __shared__ __align__(16) float As[2][BKK][BM];
    __shared__ __align__(16) float Bs[2][BKK][BN];

    const int tid = threadIdx.x;

    const float* __restrict__ B;
    const float* bias;
    float* C;
    int kStart, bn;
    if (a.mode == 1) {
        B = a.B[0]; bias = nullptr;
        C = a.C[0] + (size_t)blockIdx.z * a.M * a.N;
        kStart = blockIdx.z * a.kPerZ;
        bn = blockIdx.x * BN;
    } else {
        const int tilesPerMat = a.N / BN;
        const int sel = blockIdx.x / tilesPerMat;
        B = a.B[sel]; bias = a.bias[sel]; C = a.C[sel];
        kStart = 0;
        bn = (blockIdx.x - sel * tilesPerMat) * BN;
    }
    const int bm = blockIdx.y * BM;

    const int colb = (tid & 15) * 4;
    const int rowb = (tid >> 4) * 8;
    const int am = tid >> 1;
    const int ak = (tid & 1) * 8;
    const int bkr = tid >> 3;
    const int bn8 = (tid & 7) * 8;

    const float* Aptr = a.A + (size_t)(bm + am) * a.lda + kStart + ak;
    const float* Bptr = B + (size_t)(kStart + bkr) * a.N + bn + bn8;

    float acc[8][4] = {};
    const int nIter = a.kPerZ / BKK;

    float4 av0 = *(const float4*)(Aptr);
    float4 av1 = *(const float4*)(Aptr + 4);
    float4 bv0 = *(const float4*)(Bptr);
    float4 bv1 = *(const float4*)(Bptr + 4);
    As[0][ak + 0][am] = av0.x; As[0][ak + 1][am] = av0.y;
    As[0][ak + 2][am] = av0.z; As[0][ak + 3][am] = av0.w;
    As[0][ak + 4][am] = av1.x; As[0][ak + 5][am] = av1.y;
    As[0][ak + 6][am] = av1.z; As[0][ak + 7][am] = av1.w;
    *(float4*)&Bs[0][bkr][bn8]     = bv0;
    *(float4*)&Bs[0][bkr][bn8 + 4] = bv1;
    __syncthreads();

    for (int it = 0; it < nIter; it++) {
        const int cur = it & 1;
        const int nxt = cur ^ 1;
        const bool more = (it + 1) < nIter;

        if (more) {
            const int k0 = (it + 1) * BKK;
            av0 = *(const float4*)(Aptr + k0);
            av1 = *(const float4*)(Aptr + k0 + 4);
            bv0 = *(const float4*)(Bptr + (size_t)k0 * a.N);
            bv1 = *(const float4*)(Bptr + (size_t)k0 * a.N + 4);
        }

        #pragma unroll
        for (int k = 0; k < BKK; k++) {
            float4 a0 = *(const float4*)&As[cur][k][rowb];
            float4 a1 = *(const float4*)&As[cur][k][rowb + 4];
            float4 b  = *(const float4*)&Bs[cur][k][colb];
            float ar[8] = {a0.x,a0.y,a0.z,a0.w,a1.x,a1.y,a1.z,a1.w};
            float br[4] = {b.x,b.y,b.z,b.w};
            #pragma unroll
            for (int r = 0; r < 8; r++)
                #pragma unroll
                for (int c = 0; c < 4; c++)
                    acc[r][c] = fmaf(ar[r], br[c], acc[r][c]);
        }

        if (more) {
            As[nxt][ak + 0][am] = av0.x; As[nxt][ak + 1][am] = av0.y;
            As[nxt][ak + 2][am] = av0.z; As[nxt][ak + 3][am] = av0.w;
            As[nxt][ak + 4][am] = av1.x; As[nxt][ak + 5][am] = av1.y;
            As[nxt][ak + 6][am] = av1.z; As[nxt][ak + 7][am] = av1.w;
            *(float4*)&Bs[nxt][bkr][bn8]     = bv0;
            *(float4*)&Bs[nxt][bkr][bn8 + 4] = bv1;
            __syncthreads();
        }
    }

    float4 bb = {0.f, 0.f, 0.f, 0.f};
    if (bias) bb = *(const float4*)&bias[bn + colb];
    #pragma unroll
    for (int r = 0; r < 8; r++) {
        float4 o;
        o.x = acc[r][0] + bb.x;
        o.y = acc[r][1] + bb.y;
        o.z = acc[r][2] + bb.z;
        o.w = acc[r][3] + bb.w;
        if (a.relu) {
            o.x = fmaxf(o.x, 0.f); o.y = fmaxf(o.y, 0.f);
            o.z = fmaxf(o.z, 0.f); o.w = fmaxf(o.w, 0.f);
        }
        *(float4*)&C[(size_t)(bm + rowb + r) * a.N + bn + colb] = o;
    }
}

// ---------------------------------------------------------------------------
// Attention: per (b,i) CTA, per-dx-channel softmax over j, single pass.
// rowBase selects which global rows this launch covers.
// ---------------------------------------------------------------------------
__global__ __launch_bounds__(256)
void attn_kernel(const float* __restrict__ Q, const float* __restrict__ K,
                 const float* __restrict__ V, const float* __restrict__ e_add,
                 const float* __restrict__ e_mul,
                 const float* __restrict__ y_add, const float* __restrict__ y_mul,
                 const float* __restrict__ mask, float* __restrict__ T,
                 int rowBase)
{
    const int blk = rowBase + blockIdx.x;      // global row = b*NN + i
    const int b   = blk >> 8;
    const int dx  = threadIdx.x;

    const float scale = 0.17677669529663687f;  // 1/sqrt(32)
    const float mi = mask[blk];
    const float q  = Q[(size_t)blk * DX + dx] * mi * scale;

    const float* __restrict__ ea = e_add + (size_t)blk * (NN * DX) + dx;
    const float* __restrict__ em = e_mul + (size_t)blk * (NN * DX) + dx;
    const float* __restrict__ kb = K + (size_t)b * (NN * DX) + dx;
    const float* __restrict__ vb = V + (size_t)b * (NN * DX) + dx;
    const float* __restrict__ mrow = mask + b * NN;

    float s = 0.f, acc = 0.f;

    #pragma unroll 8
    for (int j = 0; j < NN; j++) {
        float mj  = mrow[j];
        float ee  = mi * mj;
        float emv = em[(size_t)j * DX];
        float eav = ea[(size_t)j * DX];
        float kv  = kb[(size_t)j * DX];
        float vv  = vb[(size_t)j * DX];
        float y = fmaf(q * kv, fmaf(emv, ee, 1.f), eav * ee);
        float p = __expf(y - 10.f) * mj;
        s += p;
        acc = fmaf(p, vv, acc);
    }

    float wv = acc / s;
    float t = fmaf(y_mul[b * DX + dx] + 1.f, wv, y_add[b * DX + dx]);
    T[(size_t)blk * DX + dx] = t;
}

// ---------------------------------------------------------------------------
// Fused split-K reduce + bias + residual + LayerNorm (per-half launch):
// v = base[row,t] + mask_row * (sum_z P[z*pstride + row*DX + t] + bias[t])
// ---------------------------------------------------------------------------
__global__ __launch_bounds__(256)
void ln_kernel(const float* __restrict__ base, const float* __restrict__ P,
               int nsplit, int pstride, const float* __restrict__ bias,
               const float* __restrict__ mask,
               const float* __restrict__ g, const float* __restrict__ beta,
               float* __restrict__ out)
{
    const int row = blockIdx.x;                // local row within this launch
    const int t   = threadIdx.x;
    const size_t off = (size_t)row * DX + t;

    float add = bias[t];
    #pragma unroll 4
    for (int z = 0; z < nsplit; z++)
        add += P[(size_t)z * pstride + off];

    float mrow = mask ? mask[row] : 1.f;
    float v = base[off] + add * mrow;

    float s1 = v, s2 = v * v;
    #pragma unroll
    for (int o = 16; o > 0; o >>= 1) {
        s1 += __shfl_xor_sync(0xffffffffu, s1, o);
        s2 += __shfl_xor_sync(0xffffffffu, s2, o);
    }
    __shared__ float sh1[8], sh2[8];
    const int w = t >> 5, l = t & 31;
    if (l == 0) { sh1[w] = s1; sh2[w] = s2; }
    __syncthreads();
    if (w == 0) {
        float aa = (l < 8) ? sh1[l] : 0.f;
        float cc = (l < 8) ? sh2[l] : 0.f;
        #pragma unroll
        for (int o = 4; o > 0; o >>= 1) {
            aa += __shfl_xor_sync(0xffffffffu, aa, o);
            cc += __shfl_xor_sync(0xffffffffu, cc, o);
        }
        if (l == 0) { sh1[0] = aa; sh2[0] = cc; }
    }
    __syncthreads();

    float mu  = sh1[0] * (1.f / DX);
    float var = sh2[0] * (1.f / DX) - mu * mu;
    float rs  = rsqrtf(var + EPS);
    out[off] = fmaf((v - mu) * rs, g[t], beta[t]);
}

// ---------------------------------------------------------------------------
// Launch: forked-capture pipeline. Stream 0 streams attention (HBM-bound);
// stream s2 runs the compute-bound GEMM/LN tail per half, overlapped.
// ---------------------------------------------------------------------------
extern "C" void kernel_launch(void* const* d_in, const int* in_sizes, int n_in,
                              void* d_out, int out_size)
{
    const float* X       = (const float*)d_in[0];
    const float* e_add   = (const float*)d_in[1];
    const float* e_mul   = (const float*)d_in[2];
    const float* y_x_add = (const float*)d_in[3];
    const float* y_x_mul = (const float*)d_in[4];
    const float* nmask   = (const float*)d_in[5];
    const float* Wq      = (const float*)d_in[6];
    const float* bq      = (const float*)d_in[7];
    const float* Wk      = (const float*)d_in[8];
    const float* bk      = (const float*)d_in[9];
    const float* Wv      = (const float*)d_in[10];
    const float* bv      = (const float*)d_in[11];
    const float* Wo      = (const float*)d_in[12];
    const float* bo      = (const float*)d_in[13];
    const float* W1      = (const float*)d_in[14];
    const float* b1      = (const float*)d_in[15];
    const float* W2      = (const float*)d_in[16];
    const float* b2      = (const float*)d_in[17];
    const float* g1      = (const float*)d_in[18];
    const float* beta1   = (const float*)d_in[19];
    const float* g2      = (const float*)d_in[20];
    const float* beta2   = (const float*)d_in[21];
    float* out = (float*)d_out;

    float *Qb, *Kb, *Vb, *Tb, *X1b, *Hb, *Pb;
    cudaGetSymbolAddress((void**)&Qb,  g_Q);
    cudaGetSymbolAddress((void**)&Kb,  g_K);
    cudaGetSymbolAddress((void**)&Vb,  g_V);
    cudaGetSymbolAddress((void**)&Tb,  g_T);
    cudaGetSymbolAddress((void**)&X1b, g_X1);
    cudaGetSymbolAddress((void**)&Hb,  g_H);
    cudaGetSymbolAddress((void**)&Pb,  g_P);

    static cudaStream_t s2 = nullptr;
    static cudaEvent_t evA[2] = {nullptr, nullptr};
    static cudaEvent_t evJoin = nullptr;
    if (!s2) {
        cudaStreamCreateWithFlags(&s2, cudaStreamNonBlocking);
        cudaEventCreateWithFlags(&evA[0], cudaEventDisableTiming);
        cudaEventCreateWithFlags(&evA[1], cudaEventDisableTiming);
        cudaEventCreateWithFlags(&evJoin, cudaEventDisableTiming);
    }

    // 1) QKV projections (full, 192 CTAs) on stream 0
    {
        GArgs a = {};
        a.A = X;
        a.B[0] = Wq; a.B[1] = Wk; a.B[2] = Wv;
        a.bias[0] = bq; a.bias[1] = bk; a.bias[2] = bv;
        a.C[0] = Qb; a.C[1] = Kb; a.C[2] = Vb;
        a.M = ROWS; a.N = DX; a.lda = DX; a.kPerZ = DX; a.relu = 0; a.mode = 0;
        dim3 grid(3 * DX / BN, ROWS / BM, 1);
        sgemm_kernel<<<grid, 128>>>(a);
    }

    // 2) attention halves on stream 0, with fork events
    for (int h = 0; h < 2; h++) {
        attn_kernel<<<HROWS, 256>>>(Qb, Kb, Vb, e_add, e_mul,
                                    y_x_add, y_x_mul, nmask, Tb, h * HROWS);
        cudaEventRecord(evA[h], 0);
    }

    // 3) per-half tails on s2, each gated on its attention half
    const int HMN = HROWS * DX;              // 512*256
    for (int h = 0; h < 2; h++) {
        cudaStreamWaitEvent(s2, evA[h], 0);
        const int rb = h * HROWS;
        float* Ph = Pb + (size_t)h * 4 * HMN;

        // Wo partials (split-K=2, 64 CTAs)
        {
            GArgs a = {};
            a.A = Tb + (size_t)rb * DX; a.B[0] = Wo; a.C[0] = Ph;
            a.M = HROWS; a.N = DX; a.lda = DX; a.kPerZ = DX / 2; a.relu = 0; a.mode = 1;
            dim3 grid(DX / BN, HROWS / BM, 2);
            sgemm_kernel<<<grid, 128, 0, s2>>>(a);
        }
        // X1 = LN(X + mask*(sum P + bo))
        ln_kernel<<<HROWS, 256, 0, s2>>>(X + (size_t)rb * DX, Ph, 2, HMN, bo,
                                         nmask + rb, g1, beta1,
                                         X1b + (size_t)rb * DX);
        // H = relu(X1 @ W1 + b1)  (128 CTAs)
        {
            GArgs a = {};
            a.A = X1b + (size_t)rb * DX; a.B[0] = W1; a.bias[0] = b1;
            a.C[0] = Hb + (size_t)rb * DFF;
            a.M = HROWS; a.N = DFF; a.lda = DX; a.kPerZ = DX; a.relu = 1; a.mode = 0;
            dim3 grid(DFF / BN, HROWS / BM, 1);
            sgemm_kernel<<<grid, 128, 0, s2>>>(a);
        }
        // W2 partials (split-K=4, 128 CTAs)
        {
            GArgs a = {};
            a.A = Hb + (size_t)rb * DFF; a.B[0] = W2; a.C[0] = Ph;
            a.M = HROWS; a.N = DX; a.lda = DFF; a.kPerZ = DFF / 4; a.relu = 0; a.mode = 1;
            dim3 grid(DX / BN, HROWS / BM, 4);
            sgemm_kernel<<<grid, 128, 0, s2>>>(a);
        }
        // out = LN(X1 + sum P + b2)
        ln_kernel<<<HROWS, 256, 0, s2>>>(X1b + (size_t)rb * DX, Ph, 4, HMN, b2,
                                         (const float*)nullptr, g2, beta2,
                                         out + (size_t)rb * DX);
    }

    // 4) join s2 back into stream 0 before capture ends
    cudaEventRecord(evJoin, s2);
    cudaStreamWaitEvent(0, evJoin, 0);
}

// round 7
// speedup vs baseline: 1.7288x; 1.7288x over previous
#include <cuda_runtime.h>
#include <cuda_bf16.h>
#include <math.h>
#include <stdint.h>

// ---------------------------------------------------------------------------
// Problem constants
// ---------------------------------------------------------------------------
#define BS 4
#define NN 256
#define DX 256
#define HH 8
#define DF 32
#define DFF 1024
#define ROWS (BS * NN)            // 1024
#define EPS 1e-5f
#define JSPLIT 2
#define JCHUNK (NN / JSPLIT)      // 128

// ---------------------------------------------------------------------------
// Device scratch (no allocations allowed)
// ---------------------------------------------------------------------------
__device__ float g_Q [ROWS * DX];
__device__ float g_K [ROWS * DX];
__device__ float g_V [ROWS * DX];
__device__ float g_T [ROWS * DX];
__device__ float g_X1[ROWS * DX];
__device__ float g_H [ROWS * DFF];
__device__ float g_P [4 * ROWS * DX];         // split-K partials
__device__ float2 g_SA[JSPLIT * ROWS * DX];   // attn partials (s, acc)

// ---------------------------------------------------------------------------
// Double-buffered SGEMM: BM=BN=64, BK=16, 128 threads, 8x4 micro-tile,
// ping-pong SMEM, 1 sync/iter.
// mode 0: fused-N (blockIdx.x spans matrices; bias added here)
// mode 1: split-K (blockIdx.z = K-chunk; partial to C + z*M*N; bias deferred)
// ---------------------------------------------------------------------------
struct GArgs {
    const float* A;
    const float* B[3];
    const float* bias[3];
    float* C[3];
    int M, N, lda;      // N = per-matrix width; lda = A row stride
    int kPerZ;
    int relu, mode;
};

#define BM 64
#define BN 64
#define BKK 16

__global__ __launch_bounds__(128)
void sgemm_kernel(GArgs a)
{
    __shared__ __align__(16) float As[2][BKK][BM];
    __shared__ __align__(16) float Bs[2][BKK][BN];

    const int tid = threadIdx.x;

    const float* __restrict__ B;
    const float* bias;
    float* C;
    int kStart, bn;
    if (a.mode == 1) {
        B = a.B[0]; bias = nullptr;
        C = a.C[0] + (size_t)blockIdx.z * a.M * a.N;
        kStart = blockIdx.z * a.kPerZ;
        bn = blockIdx.x * BN;
    } else {
        const int tilesPerMat = a.N / BN;
        const int sel = blockIdx.x / tilesPerMat;
        B = a.B[sel]; bias = a.bias[sel]; C = a.C[sel];
        kStart = 0;
        bn = (blockIdx.x - sel * tilesPerMat) * BN;
    }
    const int bm = blockIdx.y * BM;

    const int colb = (tid & 15) * 4;
    const int rowb = (tid >> 4) * 8;
    const int am = tid >> 1;
    const int ak = (tid & 1) * 8;
    const int bkr = tid >> 3;
    const int bn8 = (tid & 7) * 8;

    const float* Aptr = a.A + (size_t)(bm + am) * a.lda + kStart + ak;
    const float* Bptr = B + (size_t)(kStart + bkr) * a.N + bn + bn8;

    float acc[8][4] = {};
    const int nIter = a.kPerZ / BKK;

    float4 av0 = *(const float4*)(Aptr);
    float4 av1 = *(const float4*)(Aptr + 4);
    float4 bv0 = *(const float4*)(Bptr);
    float4 bv1 = *(const float4*)(Bptr + 4);
    As[0][ak + 0][am] = av0.x; As[0][ak + 1][am] = av0.y;
    As[0][ak + 2][am] = av0.z; As[0][ak + 3][am] = av0.w;
    As[0][ak + 4][am] = av1.x; As[0][ak + 5][am] = av1.y;
    As[0][ak + 6][am] = av1.z; As[0][ak + 7][am] = av1.w;
    *(float4*)&Bs[0][bkr][bn8]     = bv0;
    *(float4*)&Bs[0][bkr][bn8 + 4] = bv1;
    __syncthreads();

    for (int it = 0; it < nIter; it++) {
        const int cur = it & 1;
        const int nxt = cur ^ 1;
        const bool more = (it + 1) < nIter;

        if (more) {
            const int k0 = (it + 1) * BKK;
            av0 = *(const float4*)(Aptr + k0);
            av1 = *(const float4*)(Aptr + k0 + 4);
            bv0 = *(const float4*)(Bptr + (size_t)k0 * a.N);
            bv1 = *(const float4*)(Bptr + (size_t)k0 * a.N + 4);
        }

        #pragma unroll
        for (int k = 0; k < BKK; k++) {
            float4 a0 = *(const float4*)&As[cur][k][rowb];
            float4 a1 = *(const float4*)&As[cur][k][rowb + 4];
            float4 b  = *(const float4*)&Bs[cur][k][colb];
            float ar[8] = {a0.x,a0.y,a0.z,a0.w,a1.x,a1.y,a1.z,a1.w};
            float br[4] = {b.x,b.y,b.z,b.w};
            #pragma unroll
            for (int r = 0; r < 8; r++)
                #pragma unroll
                for (int c = 0; c < 4; c++)
                    acc[r][c] = fmaf(ar[r], br[c], acc[r][c]);
        }

        if (more) {
            As[nxt][ak + 0][am] = av0.x; As[nxt][ak + 1][am] = av0.y;
            As[nxt][ak + 2][am] = av0.z; As[nxt][ak + 3][am] = av0.w;
            As[nxt][ak + 4][am] = av1.x; As[nxt][ak + 5][am] = av1.y;
            As[nxt][ak + 6][am] = av1.z; As[nxt][ak + 7][am] = av1.w;
            *(float4*)&Bs[nxt][bkr][bn8]     = bv0;
            *(float4*)&Bs[nxt][bkr][bn8 + 4] = bv1;
            __syncthreads();
        }
    }

    float4 bb = {0.f, 0.f, 0.f, 0.f};
    if (bias) bb = *(const float4*)&bias[bn + colb];
    #pragma unroll
    for (int r = 0; r < 8; r++) {
        float4 o;
        o.x = acc[r][0] + bb.x;
        o.y = acc[r][1] + bb.y;
        o.z = acc[r][2] + bb.z;
        o.w = acc[r][3] + bb.w;
        if (a.relu) {
            o.x = fmaxf(o.x, 0.f); o.y = fmaxf(o.y, 0.f);
            o.z = fmaxf(o.z, 0.f); o.w = fmaxf(o.w, 0.f);
        }
        *(float4*)&C[(size_t)(bm + rowb + r) * a.N + bn + colb] = o;
    }
}

// ---------------------------------------------------------------------------
// Attention partial: grid (ROWS, JSPLIT). CTA (row, jz) reduces j over its
// 128-j chunk with fixed-shift softmax (shift-invariant; partials additive).
// Writes (s, acc) per (jz,row,dx).
// ---------------------------------------------------------------------------
__global__ __launch_bounds__(256)
void attn_part_kernel(const float* __restrict__ Q, const float* __restrict__ K,
                      const float* __restrict__ V, const float* __restrict__ e_add,
                      const float* __restrict__ e_mul,
                      const float* __restrict__ mask, float2* __restrict__ SA)
{
    const int row = blockIdx.x;                // b*NN + i
    const int jz  = blockIdx.y;
    const int b   = row >> 8;
    const int dx  = threadIdx.x;
    const int j0  = jz * JCHUNK;

    const float scale = 0.17677669529663687f;  // 1/sqrt(32)
    const float mi = mask[row];
    const float q  = Q[(size_t)row * DX + dx] * mi * scale;

    const float* __restrict__ ea = e_add + ((size_t)row * NN + j0) * DX + dx;
    const float* __restrict__ em = e_mul + ((size_t)row * NN + j0) * DX + dx;
    const float* __restrict__ kb = K + ((size_t)b * NN + j0) * DX + dx;
    const float* __restrict__ vb = V + ((size_t)b * NN + j0) * DX + dx;
    const float* __restrict__ mrow = mask + b * NN + j0;

    float s = 0.f, acc = 0.f;

    #pragma unroll 8
    for (int j = 0; j < JCHUNK; j++) {
        float mj  = mrow[j];
        float ee  = mi * mj;
        float emv = em[(size_t)j * DX];
        float eav = ea[(size_t)j * DX];
        float kv  = kb[(size_t)j * DX];
        float vv  = vb[(size_t)j * DX];
        float y = fmaf(q * kv, fmaf(emv, ee, 1.f), eav * ee);
        float p = __expf(y - 10.f) * mj;
        s += p;
        acc = fmaf(p, vv, acc);
    }

    float2 o = { s, acc };
    SA[((size_t)jz * ROWS + row) * DX + dx] = o;
}

// ---------------------------------------------------------------------------
// Combine attn partials -> T = y_add + (y_mul+1) * (sum acc / sum s)
// ---------------------------------------------------------------------------
__global__ __launch_bounds__(256)
void attn_combine_kernel(const float2* __restrict__ SA,
                         const float* __restrict__ y_add,
                         const float* __restrict__ y_mul,
                         float* __restrict__ T)
{
    const int row = blockIdx.x;
    const int b   = row >> 8;
    const int dx  = threadIdx.x;
    const size_t off = (size_t)row * DX + dx;

    float2 p0 = SA[off];
    float2 p1 = SA[(size_t)ROWS * DX + off];
    float wv = (p0.y + p1.y) / (p0.x + p1.x);
    T[off] = fmaf(y_mul[b * DX + dx] + 1.f, wv, y_add[b * DX + dx]);
}

// ---------------------------------------------------------------------------
// Fused split-K reduce + bias + residual + LayerNorm:
// v = base[row,t] + mask_row * (sum_z P[z][row,t] + bias[t])
// ---------------------------------------------------------------------------
__global__ __launch_bounds__(256)
void ln_kernel(const float* __restrict__ base, const float* __restrict__ P,
               int nsplit, const float* __restrict__ bias,
               const float* __restrict__ mask,
               const float* __restrict__ g, const float* __restrict__ beta,
               float* __restrict__ out)
{
    const int row = blockIdx.x;
    const int t   = threadIdx.x;
    const size_t MN = (size_t)ROWS * DX;
    const size_t off = (size_t)row * DX + t;

    float add = bias[t];
    #pragma unroll 4
    for (int z = 0; z < nsplit; z++)
        add += P[z * MN + off];

    float mrow = mask ? mask[row] : 1.f;
    float v = base[off] + add * mrow;

    float s1 = v, s2 = v * v;
    #pragma unroll
    for (int o = 16; o > 0; o >>= 1) {
        s1 += __shfl_xor_sync(0xffffffffu, s1, o);
        s2 += __shfl_xor_sync(0xffffffffu, s2, o);
    }
    __shared__ float sh1[8], sh2[8];
    const int w = t >> 5, l = t & 31;
    if (l == 0) { sh1[w] = s1; sh2[w] = s2; }
    __syncthreads();
    if (w == 0) {
        float aa = (l < 8) ? sh1[l] : 0.f;
        float cc = (l < 8) ? sh2[l] : 0.f;
        #pragma unroll
        for (int o = 4; o > 0; o >>= 1) {
            aa += __shfl_xor_sync(0xffffffffu, aa, o);
            cc += __shfl_xor_sync(0xffffffffu, cc, o);
        }
        if (l == 0) { sh1[0] = aa; sh2[0] = cc; }
    }
    __syncthreads();

    float mu  = sh1[0] * (1.f / DX);
    float var = sh2[0] * (1.f / DX) - mu * mu;
    float rs  = rsqrtf(var + EPS);
    out[off] = fmaf((v - mu) * rs, g[t], beta[t]);
}

// ---------------------------------------------------------------------------
// Launch (strictly serial, single stream)
// ---------------------------------------------------------------------------
extern "C" void kernel_launch(void* const* d_in, const int* in_sizes, int n_in,
                              void* d_out, int out_size)
{
    const float* X       = (const float*)d_in[0];
    const float* e_add   = (const float*)d_in[1];
    const float* e_mul   = (const float*)d_in[2];
    const float* y_x_add = (const float*)d_in[3];
    const float* y_x_mul = (const float*)d_in[4];
    const float* nmask   = (const float*)d_in[5];
    const float* Wq      = (const float*)d_in[6];
    const float* bq      = (const float*)d_in[7];
    const float* Wk      = (const float*)d_in[8];
    const float* bk      = (const float*)d_in[9];
    const float* Wv      = (const float*)d_in[10];
    const float* bv      = (const float*)d_in[11];
    const float* Wo      = (const float*)d_in[12];
    const float* bo      = (const float*)d_in[13];
    const float* W1      = (const float*)d_in[14];
    const float* b1      = (const float*)d_in[15];
    const float* W2      = (const float*)d_in[16];
    const float* b2      = (const float*)d_in[17];
    const float* g1      = (const float*)d_in[18];
    const float* beta1   = (const float*)d_in[19];
    const float* g2      = (const float*)d_in[20];
    const float* beta2   = (const float*)d_in[21];
    float* out = (float*)d_out;

    float *Qb, *Kb, *Vb, *Tb, *X1b, *Hb, *Pb;
    float2* SAb;
    cudaGetSymbolAddress((void**)&Qb,  g_Q);
    cudaGetSymbolAddress((void**)&Kb,  g_K);
    cudaGetSymbolAddress((void**)&Vb,  g_V);
    cudaGetSymbolAddress((void**)&Tb,  g_T);
    cudaGetSymbolAddress((void**)&X1b, g_X1);
    cudaGetSymbolAddress((void**)&Hb,  g_H);
    cudaGetSymbolAddress((void**)&Pb,  g_P);
    cudaGetSymbolAddress((void**)&SAb, g_SA);

    // 1) QKV projections, fused along N (192 CTAs)
    {
        GArgs a = {};
        a.A = X;
        a.B[0] = Wq; a.B[1] = Wk; a.B[2] = Wv;
        a.bias[0] = bq; a.bias[1] = bk; a.bias[2] = bv;
        a.C[0] = Qb; a.C[1] = Kb; a.C[2] = Vb;
        a.M = ROWS; a.N = DX; a.lda = DX; a.kPerZ = DX; a.relu = 0; a.mode = 0;
        dim3 grid(3 * DX / BN, ROWS / BM, 1);
        sgemm_kernel<<<grid, 128>>>(a);
    }

    // 2) attention partials (2048 CTAs) + combine -> T
    {
        dim3 grid(ROWS, JSPLIT);
        attn_part_kernel<<<grid, 256>>>(Qb, Kb, Vb, e_add, e_mul, nmask, SAb);
    }
    attn_combine_kernel<<<ROWS, 256>>>(SAb, y_x_add, y_x_mul, Tb);

    // 3) Wo partials (split-K=2, 128 CTAs); bias folded into LN1
    {
        GArgs a = {};
        a.A = Tb; a.B[0] = Wo; a.C[0] = Pb;
        a.M = ROWS; a.N = DX; a.lda = DX; a.kPerZ = DX / 2; a.relu = 0; a.mode = 1;
        dim3 grid(DX / BN, ROWS / BM, 2);
        sgemm_kernel<<<grid, 128>>>(a);
    }

    // 4) X1 = LN(X + mask*(sum P + bo))
    ln_kernel<<<ROWS, 256>>>(X, Pb, 2, bo, nmask, g1, beta1, X1b);

    // 5) H = relu(X1 @ W1 + b1)  (256 CTAs)  [6th launch -> ncu sample]
    {
        GArgs a = {};
        a.A = X1b; a.B[0] = W1; a.bias[0] = b1; a.C[0] = Hb;
        a.M = ROWS; a.N = DFF; a.lda = DX; a.kPerZ = DX; a.relu = 1; a.mode = 0;
        dim3 grid(DFF / BN, ROWS / BM, 1);
        sgemm_kernel<<<grid, 128>>>(a);
    }

    // 6) W2 partials (split-K=4, 256 CTAs); bias folded into LN2
    {
        GArgs a = {};
        a.A = Hb; a.B[0] = W2; a.C[0] = Pb;
        a.M = ROWS; a.N = DX; a.lda = DFF; a.kPerZ = DFF / 4; a.relu = 0; a.mode = 1;
        dim3 grid(DX / BN, ROWS / BM, 4);
        sgemm_kernel<<<grid, 128>>>(a);
    }

    // 7) out = LN(X1 + sum P + b2)
    ln_kernel<<<ROWS, 256>>>(X1b, Pb, 4, b2, (const float*)nullptr, g2, beta2, out);
}

// round 8
// speedup vs baseline: 2.0014x; 1.1577x over previous
#include <cuda_runtime.h>
#include <cuda_bf16.h>
#include <math.h>
#include <stdint.h>

// ---------------------------------------------------------------------------
// Problem constants
// ---------------------------------------------------------------------------
#define BS 4
#define NN 256
#define DX 256
#define HH 8
#define DF 32
#define DFF 1024
#define ROWS (BS * NN)            // 1024
#define EPS 1e-5f

// ---------------------------------------------------------------------------
// Device scratch (no allocations allowed)
// ---------------------------------------------------------------------------
__device__ float g_Q [ROWS * DX];
__device__ float g_K [ROWS * DX];
__device__ float g_V [ROWS * DX];
__device__ float g_T [ROWS * DX];
__device__ float g_X1[ROWS * DX];
__device__ float g_H [ROWS * DFF];
__device__ float g_P [4 * ROWS * DX];         // split-K partials

// ---------------------------------------------------------------------------
// Double-buffered SGEMM: BM=32, BN=64, BK=16, 128 threads, 4x4 micro-tile,
// ping-pong SMEM, 1 sync/iter. Small tile -> big grid -> latency hiding.
// mode 0: fused-N (blockIdx.x spans matrices; bias added here)
// mode 1: split-K (blockIdx.z = K-chunk; partial to C + z*M*N; bias deferred)
// ---------------------------------------------------------------------------
struct GArgs {
    const float* A;
    const float* B[3];
    const float* bias[3];
    float* C[3];
    int M, N, lda;      // N = per-matrix width; lda = A row stride
    int kPerZ;
    int relu, mode;
};

#define BM 32
#define BN 64
#define BKK 16

__global__ __launch_bounds__(128)
void sgemm_kernel(GArgs a)
{
    __shared__ __align__(16) float As[2][BKK][BM];
    __shared__ __align__(16) float Bs[2][BKK][BN];

    const int tid = threadIdx.x;

    const float* __restrict__ B;
    const float* bias;
    float* C;
    int kStart, bn;
    if (a.mode == 1) {
        B = a.B[0]; bias = nullptr;
        C = a.C[0] + (size_t)blockIdx.z * a.M * a.N;
        kStart = blockIdx.z * a.kPerZ;
        bn = blockIdx.x * BN;
    } else {
        const int tilesPerMat = a.N / BN;
        const int sel = blockIdx.x / tilesPerMat;
        B = a.B[sel]; bias = a.bias[sel]; C = a.C[sel];
        kStart = 0;
        bn = (blockIdx.x - sel * tilesPerMat) * BN;
    }
    const int bm = blockIdx.y * BM;

    // compute mapping: 16 col-groups x 8 row-groups
    const int colb = (tid & 15) * 4;          // 0..60
    const int rowb = (tid >> 4) * 4;          // 0..28
    // A load: row am (0..31), 4 consecutive k
    const int am = tid >> 2;
    const int ak = (tid & 3) * 4;             // 0,4,8,12
    // B load: row bkr (0..15), 8 consecutive n
    const int bkr = tid >> 3;
    const int bn8 = (tid & 7) * 8;            // 0..56

    const float* Aptr = a.A + (size_t)(bm + am) * a.lda + kStart + ak;
    const float* Bptr = B + (size_t)(kStart + bkr) * a.N + bn + bn8;

    float acc[4][4] = {};
    const int nIter = a.kPerZ / BKK;

    // prologue: stage tile 0
    float4 av  = *(const float4*)(Aptr);
    float4 bv0 = *(const float4*)(Bptr);
    float4 bv1 = *(const float4*)(Bptr + 4);
    As[0][ak + 0][am] = av.x; As[0][ak + 1][am] = av.y;
    As[0][ak + 2][am] = av.z; As[0][ak + 3][am] = av.w;
    *(float4*)&Bs[0][bkr][bn8]     = bv0;
    *(float4*)&Bs[0][bkr][bn8 + 4] = bv1;
    __syncthreads();

    for (int it = 0; it < nIter; it++) {
        const int cur = it & 1;
        const int nxt = cur ^ 1;
        const bool more = (it + 1) < nIter;

        if (more) {
            const int k0 = (it + 1) * BKK;
            av  = *(const float4*)(Aptr + k0);
            bv0 = *(const float4*)(Bptr + (size_t)k0 * a.N);
            bv1 = *(const float4*)(Bptr + (size_t)k0 * a.N + 4);
        }

        #pragma unroll
        for (int k = 0; k < BKK; k++) {
            float4 a4 = *(const float4*)&As[cur][k][rowb];
            float4 b4 = *(const float4*)&Bs[cur][k][colb];
            float ar[4] = {a4.x, a4.y, a4.z, a4.w};
            float br[4] = {b4.x, b4.y, b4.z, b4.w};
            #pragma unroll
            for (int r = 0; r < 4; r++)
                #pragma unroll
                for (int c = 0; c < 4; c++)
                    acc[r][c] = fmaf(ar[r], br[c], acc[r][c]);
        }

        if (more) {
            As[nxt][ak + 0][am] = av.x; As[nxt][ak + 1][am] = av.y;
            As[nxt][ak + 2][am] = av.z; As[nxt][ak + 3][am] = av.w;
            *(float4*)&Bs[nxt][bkr][bn8]     = bv0;
            *(float4*)&Bs[nxt][bkr][bn8 + 4] = bv1;
            __syncthreads();
        }
    }

    float4 bb = {0.f, 0.f, 0.f, 0.f};
    if (bias) bb = *(const float4*)&bias[bn + colb];
    #pragma unroll
    for (int r = 0; r < 4; r++) {
        float4 o;
        o.x = acc[r][0] + bb.x;
        o.y = acc[r][1] + bb.y;
        o.z = acc[r][2] + bb.z;
        o.w = acc[r][3] + bb.w;
        if (a.relu) {
            o.x = fmaxf(o.x, 0.f); o.y = fmaxf(o.y, 0.f);
            o.z = fmaxf(o.z, 0.f); o.w = fmaxf(o.w, 0.f);
        }
        *(float4*)&C[(size_t)(bm + rowb + r) * a.N + bn + colb] = o;
    }
}

// ---------------------------------------------------------------------------
// Attention: per (b,i) CTA, per-dx-channel softmax over j, single pass.
// Fixed softmax shift (shift-invariant); branchless; p *= mask_j.
// __ldcs on the 512MB e-streams (evict-first; keep K/V hot in L2).
// ---------------------------------------------------------------------------
__global__ __launch_bounds__(256)
void attn_kernel(const float* __restrict__ Q, const float* __restrict__ K,
                 const float* __restrict__ V, const float* __restrict__ e_add,
                 const float* __restrict__ e_mul,
                 const float* __restrict__ y_add, const float* __restrict__ y_mul,
                 const float* __restrict__ mask, float* __restrict__ T)
{
    const int blk = blockIdx.x;        // b*NN + i
    const int b   = blk >> 8;
    const int dx  = threadIdx.x;

    const float scale = 0.17677669529663687f;   // 1/sqrt(32)
    const float mi = mask[blk];
    const float q  = Q[(size_t)blk * DX + dx] * mi * scale;

    const float* __restrict__ ea = e_add + (size_t)blk * (NN * DX) + dx;
    const float* __restrict__ em = e_mul + (size_t)blk * (NN * DX) + dx;
    const float* __restrict__ kb = K + (size_t)b * (NN * DX) + dx;
    const float* __restrict__ vb = V + (size_t)b * (NN * DX) + dx;
    const float* __restrict__ mrow = mask + b * NN;

    float s = 0.f, acc = 0.f;

    #pragma unroll 8
    for (int j = 0; j < NN; j++) {
        float mj  = mrow[j];
        float ee  = mi * mj;
        float emv = __ldcs(em + (size_t)j * DX);
        float eav = __ldcs(ea + (size_t)j * DX);
        float kv  = kb[(size_t)j * DX];
        float vv  = vb[(size_t)j * DX];
        float y = fmaf(q * kv, fmaf(emv, ee, 1.f), eav * ee);
        float p = __expf(y - 10.f) * mj;
        s += p;
        acc = fmaf(p, vv, acc);
    }

    float wv = acc / s;
    float t = fmaf(y_mul[b * DX + dx] + 1.f, wv, y_add[b * DX + dx]);
    T[(size_t)blk * DX + dx] = t;
}

// ---------------------------------------------------------------------------
// Fused split-K reduce + bias + residual + LayerNorm:
// v = base[row,t] + mask_row * (sum_z P[z][row,t] + bias[t])
// ---------------------------------------------------------------------------
__global__ __launch_bounds__(256)
void ln_kernel(const float* __restrict__ base, const float* __restrict__ P,
               int nsplit, const float* __restrict__ bias,
               const float* __restrict__ mask,
               const float* __restrict__ g, const float* __restrict__ beta,
               float* __restrict__ out)
{
    const int row = blockIdx.x;
    const int t   = threadIdx.x;
    const size_t MN = (size_t)ROWS * DX;
    const size_t off = (size_t)row * DX + t;

    float add = bias[t];
    #pragma unroll 4
    for (int z = 0; z < nsplit; z++)
        add += P[z * MN + off];

    float mrow = mask ? mask[row] : 1.f;
    float v = base[off] + add * mrow;

    float s1 = v, s2 = v * v;
    #pragma unroll
    for (int o = 16; o > 0; o >>= 1) {
        s1 += __shfl_xor_sync(0xffffffffu, s1, o);
        s2 += __shfl_xor_sync(0xffffffffu, s2, o);
    }
    __shared__ float sh1[8], sh2[8];
    const int w = t >> 5, l = t & 31;
    if (l == 0) { sh1[w] = s1; sh2[w] = s2; }
    __syncthreads();
    if (w == 0) {
        float aa = (l < 8) ? sh1[l] : 0.f;
        float cc = (l < 8) ? sh2[l] : 0.f;
        #pragma unroll
        for (int o = 4; o > 0; o >>= 1) {
            aa += __shfl_xor_sync(0xffffffffu, aa, o);
            cc += __shfl_xor_sync(0xffffffffu, cc, o);
        }
        if (l == 0) { sh1[0] = aa; sh2[0] = cc; }
    }
    __syncthreads();

    float mu  = sh1[0] * (1.f / DX);
    float var = sh2[0] * (1.f / DX) - mu * mu;
    float rs  = rsqrtf(var + EPS);
    out[off] = fmaf((v - mu) * rs, g[t], beta[t]);
}

// ---------------------------------------------------------------------------
// Launch (strictly serial, single stream)
// ---------------------------------------------------------------------------
extern "C" void kernel_launch(void* const* d_in, const int* in_sizes, int n_in,
                              void* d_out, int out_size)
{
    const float* X       = (const float*)d_in[0];
    const float* e_add   = (const float*)d_in[1];
    const float* e_mul   = (const float*)d_in[2];
    const float* y_x_add = (const float*)d_in[3];
    const float* y_x_mul = (const float*)d_in[4];
    const float* nmask   = (const float*)d_in[5];
    const float* Wq      = (const float*)d_in[6];
    const float* bq      = (const float*)d_in[7];
    const float* Wk      = (const float*)d_in[8];
    const float* bk      = (const float*)d_in[9];
    const float* Wv      = (const float*)d_in[10];
    const float* bv      = (const float*)d_in[11];
    const float* Wo      = (const float*)d_in[12];
    const float* bo      = (const float*)d_in[13];
    const float* W1      = (const float*)d_in[14];
    const float* b1      = (const float*)d_in[15];
    const float* W2      = (const float*)d_in[16];
    const float* b2      = (const float*)d_in[17];
    const float* g1      = (const float*)d_in[18];
    const float* beta1   = (const float*)d_in[19];
    const float* g2      = (const float*)d_in[20];
    const float* beta2   = (const float*)d_in[21];
    float* out = (float*)d_out;

    float *Qb, *Kb, *Vb, *Tb, *X1b, *Hb, *Pb;
    cudaGetSymbolAddress((void**)&Qb,  g_Q);
    cudaGetSymbolAddress((void**)&Kb,  g_K);
    cudaGetSymbolAddress((void**)&Vb,  g_V);
    cudaGetSymbolAddress((void**)&Tb,  g_T);
    cudaGetSymbolAddress((void**)&X1b, g_X1);
    cudaGetSymbolAddress((void**)&Hb,  g_H);
    cudaGetSymbolAddress((void**)&Pb,  g_P);

    // 1) QKV projections, fused along N (384 CTAs)
    {
        GArgs a = {};
        a.A = X;
        a.B[0] = Wq; a.B[1] = Wk; a.B[2] = Wv;
        a.bias[0] = bq; a.bias[1] = bk; a.bias[2] = bv;
        a.C[0] = Qb; a.C[1] = Kb; a.C[2] = Vb;
        a.M = ROWS; a.N = DX; a.lda = DX; a.kPerZ = DX; a.relu = 0; a.mode = 0;
        dim3 grid(3 * DX / BN, ROWS / BM, 1);
        sgemm_kernel<<<grid, 128>>>(a);
    }

    // 2) streaming softmax attention -> T (1024 CTAs)
    attn_kernel<<<ROWS, 256>>>(Qb, Kb, Vb, e_add, e_mul, y_x_add, y_x_mul, nmask, Tb);

    // 3) Wo partials (split-K=2, 256 CTAs); bias folded into LN1
    {
        GArgs a = {};
        a.A = Tb; a.B[0] = Wo; a.C[0] = Pb;
        a.M = ROWS; a.N = DX; a.lda = DX; a.kPerZ = DX / 2; a.relu = 0; a.mode = 1;
        dim3 grid(DX / BN, ROWS / BM, 2);
        sgemm_kernel<<<grid, 128>>>(a);
    }

    // 4) X1 = LN(X + mask*(sum P + bo))
    ln_kernel<<<ROWS, 256>>>(X, Pb, 2, bo, nmask, g1, beta1, X1b);

    // 5) H = relu(X1 @ W1 + b1)  (512 CTAs)
    {
        GArgs a = {};
        a.A = X1b; a.B[0] = W1; a.bias[0] = b1; a.C[0] = Hb;
        a.M = ROWS; a.N = DFF; a.lda = DX; a.kPerZ = DX; a.relu = 1; a.mode = 0;
        dim3 grid(DFF / BN, ROWS / BM, 1);
        sgemm_kernel<<<grid, 128>>>(a);
    }

    // 6) W2 partials (split-K=4, 512 CTAs); bias folded into LN2
    {
        GArgs a = {};
        a.A = Hb; a.B[0] = W2; a.C[0] = Pb;
        a.M = ROWS; a.N = DX; a.lda = DFF; a.kPerZ = DFF / 4; a.relu = 0; a.mode = 1;
        dim3 grid(DX / BN, ROWS / BM, 4);
        sgemm_kernel<<<grid, 128>>>(a);
    }

    // 7) out = LN(X1 + sum P + b2)
    ln_kernel<<<ROWS, 256>>>(X1b, Pb, 4, b2, (const float*)nullptr, g2, beta2, out);
}